// round 9
// baseline (speedup 1.0000x reference)
#include <cuda_runtime.h>
#include <cstddef>

// ---------------------------------------------------------------------------
// FullGapModel, specialized: D = 128, P = 1, zeta = 2.
// out[s] = sum_{atoms a in s} ps_a^T Q ps_a / ||ps_a||^2,
//   Q = sum_m w[seg_sup[m]] * sp_m sp_m^T  (128x128).
// Main kernel uses packed fp32x2 FMA (fma.rn.f32x2) pairing over i-indices.
// ---------------------------------------------------------------------------

#define DIMS 128
constexpr int TILE_ATOMS = 64;
constexpr int THREADS_B  = 512;
constexpr int MAX_ATOMS  = 131072;   // >= N = 100000
constexpr int QP_BLOCKS  = 80;       // partial-Q parallelism over M
constexpr int MAX_STRUCT = 8192;     // >= S = 2000

__device__ float g_Q[DIMS * DIMS];
__device__ float g_Qpart[QP_BLOCKS][DIMS * DIMS];
__device__ float g_atomval[MAX_ATOMS];
__device__ int   g_start[MAX_STRUCT + 1];

// ---------------- f32x2 packed helpers -------------------------------------
typedef unsigned long long u64;

__device__ __forceinline__ u64 f2_pack(float x, float y) {
    u64 r; asm("mov.b64 %0, {%1, %2};" : "=l"(r) : "f"(x), "f"(y)); return r;
}
__device__ __forceinline__ float2 f2_unpack(u64 v) {
    float2 r; asm("mov.b64 {%0, %1}, %2;" : "=f"(r.x), "=f"(r.y) : "l"(v)); return r;
}
__device__ __forceinline__ u64 f2_mul(u64 a, u64 b) {
    u64 r; asm("mul.rn.f32x2 %0, %1, %2;" : "=l"(r) : "l"(a), "l"(b)); return r;
}
__device__ __forceinline__ u64 f2_fma(u64 a, u64 b, u64 c) {
    u64 r; asm("fma.rn.f32x2 %0, %1, %2, %3;" : "=l"(r) : "l"(a), "l"(b), "l"(c)); return r;
}

// ---------------------------------------------------------------------------
// Kernel A1: partial Q over M-chunks. Thread owns 8x8 register tile of Q.
// ---------------------------------------------------------------------------
__global__ __launch_bounds__(256) void compute_Q_partial(
    const float* __restrict__ sp,
    const float* __restrict__ weights,
    const int*   __restrict__ supseg,
    int M)
{
    __shared__ float srow[8][DIMS];
    __shared__ float sw[8];

    const int chunk = (M + QP_BLOCKS - 1) / QP_BLOCKS;
    const int m_lo = blockIdx.x * chunk;
    const int m_hi = min(M, m_lo + chunk);

    const int i0 = (threadIdx.x >> 4) * 8;
    const int j0 = (threadIdx.x & 15) * 8;

    float acc[8][8];
    #pragma unroll
    for (int a = 0; a < 8; a++)
        #pragma unroll
        for (int b = 0; b < 8; b++) acc[a][b] = 0.f;

    for (int m0 = m_lo; m0 < m_hi; m0 += 8) {
        const int rows = min(8, m_hi - m0);
        __syncthreads();
        for (int idx = threadIdx.x; idx < rows * DIMS; idx += 256)
            srow[idx >> 7][idx & 127] = sp[(size_t)m0 * DIMS + idx];
        if (threadIdx.x < rows)
            sw[threadIdx.x] = weights[supseg[m0 + threadIdx.x]];
        __syncthreads();

        #pragma unroll 8
        for (int u = 0; u < rows; u++) {
            float si[8], sj[8];
            *reinterpret_cast<float4*>(&si[0]) = *reinterpret_cast<float4*>(&srow[u][i0]);
            *reinterpret_cast<float4*>(&si[4]) = *reinterpret_cast<float4*>(&srow[u][i0 + 4]);
            *reinterpret_cast<float4*>(&sj[0]) = *reinterpret_cast<float4*>(&srow[u][j0]);
            *reinterpret_cast<float4*>(&sj[4]) = *reinterpret_cast<float4*>(&srow[u][j0 + 4]);
            const float wu = sw[u];
            #pragma unroll
            for (int a = 0; a < 8; a++) {
                const float siw = wu * si[a];
                #pragma unroll
                for (int b = 0; b < 8; b++)
                    acc[a][b] = fmaf(siw, sj[b], acc[a][b]);
            }
        }
    }

    float* dst = g_Qpart[blockIdx.x];
    #pragma unroll
    for (int a = 0; a < 8; a++)
        #pragma unroll
        for (int b = 0; b < 8; b += 4)
            *reinterpret_cast<float4*>(&dst[(i0 + a) * DIMS + j0 + b]) =
                *reinterpret_cast<float4*>(&acc[a][b]);
}

// ---------------------------------------------------------------------------
// Kernel A2: deterministic reduction of the QP_BLOCKS partials.
// ---------------------------------------------------------------------------
__global__ void reduce_Q()
{
    const int idx = blockIdx.x * blockDim.x + threadIdx.x;   // 0..16383
    float s = 0.f;
    #pragma unroll 8
    for (int p = 0; p < QP_BLOCKS; p++)
        s += g_Qpart[p][idx];
    g_Q[idx] = s;
}

// ---------------------------------------------------------------------------
// Kernel D: mark structure boundaries from the sorted atom_segments array.
// Total writes across all threads = S+1 (handles empty structures).
// ---------------------------------------------------------------------------
__global__ void mark_starts(const int* __restrict__ aseg, int N, int S)
{
    const int i = blockIdx.x * blockDim.x + threadIdx.x;
    if (i >= N) return;
    const int cur = aseg[i];
    const int prev = (i == 0) ? -1 : aseg[i - 1];
    for (int s = prev + 1; s <= cur; s++) g_start[s] = i;
    if (i == N - 1) {
        for (int s = cur + 1; s <= S; s++) g_start[s] = N;
    }
}

// ---------------------------------------------------------------------------
// Kernel B: per-atom quadratic form with f32x2-packed FMAs.
// 512 threads, 64-atom tile. Thread (warp w, lane l): atoms w*4..w*4+3,
// j-cols l*4..l*4+3. Q stored in shared as (i-even, i-odd) interleaved pairs:
// sQp[(i>>1)*256 + j*2 + (i&1)], so each i-pair's 4 j-values load as LDS.128
// of natural f32x2 pairs. xx2 = (ps[a][2ip], ps[a][2ip+1]) via LDS.64.
// ---------------------------------------------------------------------------
constexpr int SMEM_B = (DIMS * DIMS + TILE_ATOMS * DIMS + TILE_ATOMS) * 4;

__global__ __launch_bounds__(THREADS_B) void atom_quadform(
    const float* __restrict__ ps, int N, int numTiles)
{
    extern __shared__ float smem[];
    float* sQp  = smem;                        // 128*128 interleaved
    float* sP   = smem + DIMS * DIMS;          // 64*128 raw ps tile
    float* sInv = sP + TILE_ATOMS * DIMS;      // 64 x 1/||ps||^2

    // Load Q into interleaved-pair layout.
    for (int idx = threadIdx.x; idx < DIMS * DIMS; idx += THREADS_B) {
        const int i = idx >> 7, j = idx & 127;
        sQp[(i >> 1) * 256 + j * 2 + (i & 1)] = g_Q[idx];
    }

    const int lane = threadIdx.x & 31;
    const int w    = threadIdx.x >> 5;         // 0..15 -> atom group of 4
    const int arow = w * 4;

    for (int tile = blockIdx.x; tile < numTiles; tile += gridDim.x) {
        const int base = tile * TILE_ATOMS;
        __syncthreads();   // sQp visible (1st iter) / previous tile reads done

        // Load 64x128 tile; 8 threads per atom row; fused sum of squares.
        {
            const int a    = threadIdx.x >> 3;   // 0..63
            const int part = threadIdx.x & 7;    // 16 floats each
            const int ga   = base + a;
            float ss = 0.f;
            #pragma unroll
            for (int q = 0; q < 4; q++) {
                const int col = part * 16 + q * 4;
                float4 v = make_float4(0.f, 0.f, 0.f, 0.f);
                if (ga < N)
                    v = *reinterpret_cast<const float4*>(ps + (size_t)ga * DIMS + col);
                *reinterpret_cast<float4*>(&sP[a * DIMS + col]) = v;
                ss = fmaf(v.x, v.x, ss);
                ss = fmaf(v.y, v.y, ss);
                ss = fmaf(v.z, v.z, ss);
                ss = fmaf(v.w, v.w, ss);
            }
            ss += __shfl_xor_sync(0xffffffffu, ss, 1);
            ss += __shfl_xor_sync(0xffffffffu, ss, 2);
            ss += __shfl_xor_sync(0xffffffffu, ss, 4);
            if (part == 0) sInv[a] = (ss > 0.f) ? 1.f / ss : 0.f;
        }
        __syncthreads();

        // Tile-constant pj values, duplicated into f32x2 once.
        u64 pjd[4][4];
        #pragma unroll
        for (int a = 0; a < 4; a++) {
            float4 v = *reinterpret_cast<float4*>(&sP[(arow + a) * DIMS + lane * 4]);
            pjd[a][0] = f2_pack(v.x, v.x);
            pjd[a][1] = f2_pack(v.y, v.y);
            pjd[a][2] = f2_pack(v.z, v.z);
            pjd[a][3] = f2_pack(v.w, v.w);
        }

        u64 acc[4];
        #pragma unroll
        for (int a = 0; a < 4; a++) acc[a] = 0ull;

        #pragma unroll 4
        for (int ip = 0; ip < DIMS / 2; ip++) {
            const u64* qp = reinterpret_cast<const u64*>(sQp + ip * 256 + lane * 8);
            const u64 q0 = qp[0], q1 = qp[1], q2 = qp[2], q3 = qp[3];
            #pragma unroll
            for (int a = 0; a < 4; a++) {
                const u64 xx = *reinterpret_cast<const u64*>(
                    sP + (arow + a) * DIMS + ip * 2);          // warp broadcast
                u64 t = f2_mul(q0, pjd[a][0]);
                t = f2_fma(q1, pjd[a][1], t);
                t = f2_fma(q2, pjd[a][2], t);
                t = f2_fma(q3, pjd[a][3], t);
                acc[a] = f2_fma(xx, t, acc[a]);
            }
        }

        // Reduce: sum pair halves, then across the 32 j-groups.
        #pragma unroll
        for (int a = 0; a < 4; a++) {
            float2 h = f2_unpack(acc[a]);
            float v = h.x + h.y;
            #pragma unroll
            for (int off = 16; off; off >>= 1)
                v += __shfl_xor_sync(0xffffffffu, v, off);
            if (lane == 0) {
                const int ga = base + arow + a;
                if (ga < N)
                    g_atomval[ga] = v * sInv[arow + a];
            }
        }
    }
}

// ---------------------------------------------------------------------------
// Kernel C: segment sum using precomputed boundaries. One warp / structure.
// ---------------------------------------------------------------------------
__global__ void seg_sum(float* __restrict__ out, int S)
{
    const int s = blockIdx.x * (blockDim.x >> 5) + (threadIdx.x >> 5);
    if (s >= S) return;
    const int lane = threadIdx.x & 31;

    const int lo = g_start[s];
    const int hi = g_start[s + 1];

    float sum = 0.f;
    for (int i = lo + lane; i < hi; i += 32)
        sum += g_atomval[i];
    #pragma unroll
    for (int off = 16; off; off >>= 1)
        sum += __shfl_xor_sync(0xffffffffu, sum, off);
    if (lane == 0) out[s] = sum;
}

// ---------------------------------------------------------------------------
// Launch.
// ---------------------------------------------------------------------------
extern "C" void kernel_launch(void* const* d_in, const int* in_sizes, int n_in,
                              void* d_out, int out_size)
{
    const float* ps   = (const float*)d_in[0];
    const float* sp   = (const float*)d_in[1];
    const float* w    = (const float*)d_in[2];
    const int*   aseg = (const int*)d_in[3];
    const int*   sseg = (const int*)d_in[4];

    const int N = in_sizes[3];
    const int M = in_sizes[4];
    const int S = out_size;          // P == 1
    float* out = (float*)d_out;

    mark_starts<<<(N + 255) / 256, 256>>>(aseg, N, S);

    compute_Q_partial<<<QP_BLOCKS, 256>>>(sp, w, sseg, M);
    reduce_Q<<<DIMS * DIMS / 256, 256>>>();

    cudaFuncSetAttribute(atom_quadform,
                         cudaFuncAttributeMaxDynamicSharedMemorySize, SMEM_B);
    const int numTiles = (N + TILE_ATOMS - 1) / TILE_ATOMS;
    const int grid = numTiles < 148 ? numTiles : 148;   // persistent, 1 CTA/SM
    atom_quadform<<<grid, THREADS_B, SMEM_B>>>(ps, N, numTiles);

    seg_sum<<<(S + 7) / 8, 256>>>(out, S);
}

// round 12
// speedup vs baseline: 2.3023x; 2.3023x over previous
#include <cuda_runtime.h>
#include <cuda_bf16.h>
#include <cstdint>
#include <cstddef>

// ---------------------------------------------------------------------------
// FullGapModel, specialized: D = 128, P = 1, zeta = 2.
// out[s] = sum_{atoms a in s} ps_a^T Q ps_a / ||ps_a||^2,
//   Q = sum_m w[seg_sup[m]] * sp_m sp_m^T  (128x128, symmetric).
// Main kernel: bf16 mma.sync (m16n8k16) GEMM Y = H * Q with Q split into
// bf16 hi+lo (both accumulated into the same f32 C), and A-side error
// compensation in the epilogue: val = dot(2*ps - h, Y) / ||ps||^2.
// ---------------------------------------------------------------------------

#define DIMS 128
constexpr int TILE_M     = 128;     // atoms per CTA tile
constexpr int THREADS_B  = 512;     // 16 warps: 4 (m) x 4 (n)
constexpr int MAX_ATOMS  = 131072;  // >= N = 100000
constexpr int QP_BLOCKS  = 80;
constexpr int MAX_STRUCT = 8192;    // >= S = 2000

__device__ float    g_Qpart[QP_BLOCKS][DIMS * DIMS];
__device__ uint32_t g_Bhi_pack[8192];   // bf16x2 fragment-packed Q hi
__device__ uint32_t g_Blo_pack[8192];   // bf16x2 fragment-packed Q lo
__device__ float    g_atomval[MAX_ATOMS];
__device__ int      g_start[MAX_STRUCT + 1];

// ---------------------------------------------------------------------------
// Kernel A1: partial Q over M-chunks. Thread owns 8x8 register tile of Q.
// ---------------------------------------------------------------------------
__global__ __launch_bounds__(256) void compute_Q_partial(
    const float* __restrict__ sp,
    const float* __restrict__ weights,
    const int*   __restrict__ supseg,
    int M)
{
    __shared__ float srow[8][DIMS];
    __shared__ float sw[8];

    const int chunk = (M + QP_BLOCKS - 1) / QP_BLOCKS;
    const int m_lo = blockIdx.x * chunk;
    const int m_hi = min(M, m_lo + chunk);

    const int i0 = (threadIdx.x >> 4) * 8;
    const int j0 = (threadIdx.x & 15) * 8;

    float acc[8][8];
    #pragma unroll
    for (int a = 0; a < 8; a++)
        #pragma unroll
        for (int b = 0; b < 8; b++) acc[a][b] = 0.f;

    for (int m0 = m_lo; m0 < m_hi; m0 += 8) {
        const int rows = min(8, m_hi - m0);
        __syncthreads();
        for (int idx = threadIdx.x; idx < rows * DIMS; idx += 256)
            srow[idx >> 7][idx & 127] = sp[(size_t)m0 * DIMS + idx];
        if (threadIdx.x < rows)
            sw[threadIdx.x] = weights[supseg[m0 + threadIdx.x]];
        __syncthreads();

        #pragma unroll 8
        for (int u = 0; u < rows; u++) {
            float si[8], sj[8];
            *reinterpret_cast<float4*>(&si[0]) = *reinterpret_cast<float4*>(&srow[u][i0]);
            *reinterpret_cast<float4*>(&si[4]) = *reinterpret_cast<float4*>(&srow[u][i0 + 4]);
            *reinterpret_cast<float4*>(&sj[0]) = *reinterpret_cast<float4*>(&srow[u][j0]);
            *reinterpret_cast<float4*>(&sj[4]) = *reinterpret_cast<float4*>(&srow[u][j0 + 4]);
            const float wu = sw[u];
            #pragma unroll
            for (int a = 0; a < 8; a++) {
                const float siw = wu * si[a];
                #pragma unroll
                for (int b = 0; b < 8; b++)
                    acc[a][b] = fmaf(siw, sj[b], acc[a][b]);
            }
        }
    }

    float* dst = g_Qpart[blockIdx.x];
    #pragma unroll
    for (int a = 0; a < 8; a++)
        #pragma unroll
        for (int b = 0; b < 8; b += 4)
            *reinterpret_cast<float4*>(&dst[(i0 + a) * DIMS + j0 + b]) =
                *reinterpret_cast<float4*>(&acc[a][b]);
}

// ---------------------------------------------------------------------------
// Kernel A2: reduce partials; emit bf16 hi/lo Q in mma fragment-packed order.
// For element (n, k): B-frag b_r of tile (t = n/8, u = k/16) at lane
// l = (n%8)*4 + ((k%8)>>1), reg r = (k%16)/8, halfword = k&1.
// ---------------------------------------------------------------------------
__global__ void reduce_Q()
{
    const int idx = blockIdx.x * blockDim.x + threadIdx.x;   // 0..16383
    const int n = idx >> 7, k = idx & 127;
    float s = 0.f;
    #pragma unroll 8
    for (int p = 0; p < QP_BLOCKS; p++)
        s += g_Qpart[p][idx];

    const __nv_bfloat16 hi = __float2bfloat16_rn(s);
    const __nv_bfloat16 lo = __float2bfloat16_rn(s - __bfloat162float(hi));

    const int u = k >> 4, t = n >> 3;
    const int g = n & 7, kk = k & 15;
    const int r = kk >> 3, tg = (kk & 7) >> 1, half = kk & 1;
    const int u32idx = ((u * 16 + t) * 32 + (g * 4 + tg)) * 2 + r;

    reinterpret_cast<__nv_bfloat16*>(g_Bhi_pack)[u32idx * 2 + half] = hi;
    reinterpret_cast<__nv_bfloat16*>(g_Blo_pack)[u32idx * 2 + half] = lo;
}

// ---------------------------------------------------------------------------
// Kernel D: structure boundaries from the sorted atom_segments array.
// ---------------------------------------------------------------------------
__global__ void mark_starts(const int* __restrict__ aseg, int N, int S)
{
    const int i = blockIdx.x * blockDim.x + threadIdx.x;
    if (i >= N) return;
    const int cur = aseg[i];
    const int prev = (i == 0) ? -1 : aseg[i - 1];
    for (int s = prev + 1; s <= cur; s++) g_start[s] = i;
    if (i == N - 1)
        for (int s = cur + 1; s <= S; s++) g_start[s] = N;
}

// ---------------------------------------------------------------------------
// Kernel B: HMMA quadratic form.
// smem: A (bf16, 128 x stride136), E = 2*ps - h (f32, 128 x stride132),
//       Bhi/Blo packed (32KB each, tile-invariant), spart[128][4], inv[128].
// ---------------------------------------------------------------------------
constexpr int A_STRIDE  = 136;                         // bf16 units
constexpr int E_STRIDE  = 132;                         // f32 units
constexpr int OFF_A     = 0;                           // 128*136*2 = 34816
constexpr int OFF_E     = 34816;                       // 128*132*4 = 67584
constexpr int OFF_BHI   = OFF_E + 67584;               // 102400, 32768 B
constexpr int OFF_BLO   = OFF_BHI + 32768;             // 135168, 32768 B
constexpr int OFF_SPART = OFF_BLO + 32768;             // 167936, 2048 B
constexpr int OFF_INV   = OFF_SPART + 2048;            // 169984, 512 B
constexpr int SMEM_TOTAL_B = OFF_INV + 512;            // 170496 B

__device__ __forceinline__ void mma_bf16(float* d, const uint32_t* a,
                                         uint32_t b0, uint32_t b1) {
    asm volatile(
        "mma.sync.aligned.m16n8k16.row.col.f32.bf16.bf16.f32 "
        "{%0,%1,%2,%3}, {%4,%5,%6,%7}, {%8,%9}, {%0,%1,%2,%3};"
        : "+f"(d[0]), "+f"(d[1]), "+f"(d[2]), "+f"(d[3])
        : "r"(a[0]), "r"(a[1]), "r"(a[2]), "r"(a[3]), "r"(b0), "r"(b1));
}

__global__ __launch_bounds__(THREADS_B) void atom_quadform_mma(
    const float* __restrict__ ps, int N, int numTiles)
{
    extern __shared__ char smem[];
    __nv_bfloat16* sA = reinterpret_cast<__nv_bfloat16*>(smem + OFF_A);
    float* sE    = reinterpret_cast<float*>(smem + OFF_E);
    float* sPart = reinterpret_cast<float*>(smem + OFF_SPART);
    float* sInv  = reinterpret_cast<float*>(smem + OFF_INV);
    const uint32_t* sBhi = reinterpret_cast<const uint32_t*>(smem + OFF_BHI);
    const uint32_t* sBlo = reinterpret_cast<const uint32_t*>(smem + OFF_BLO);

    const int tid = threadIdx.x;
    const int wid = tid >> 5;
    const int lid = tid & 31;
    const int g  = lid >> 2;
    const int tg = lid & 3;
    const int mrow0 = (wid & 3) * 32;
    const int ng    = wid >> 2;          // n column group (32 cols)

    // Stage packed B (tile-invariant) into smem once.
    {
        const uint4* srcH = reinterpret_cast<const uint4*>(g_Bhi_pack);
        const uint4* srcL = reinterpret_cast<const uint4*>(g_Blo_pack);
        uint4* dstH = reinterpret_cast<uint4*>(smem + OFF_BHI);
        uint4* dstL = reinterpret_cast<uint4*>(smem + OFF_BLO);
        for (int i = tid; i < 2048; i += THREADS_B) {
            dstH[i] = srcH[i];
            dstL[i] = srcL[i];
        }
    }

    for (int tile = blockIdx.x; tile < numTiles; tile += gridDim.x) {
        const int base = tile * TILE_M;
        __syncthreads();   // B staged (1st iter); prev tile consumed

        // ---- load phase: raw ps -> bf16 A + f32 E(=2ps-h) + inv ----
        {
            const int a    = tid >> 2;           // row 0..127
            const int part = tid & 3;            // 32 cols each
            const int ga   = base + a;
            float ss = 0.f;
            #pragma unroll
            for (int q = 0; q < 8; q++) {
                const int col = part * 32 + q * 4;
                float4 v = make_float4(0.f, 0.f, 0.f, 0.f);
                if (ga < N)
                    v = *reinterpret_cast<const float4*>(ps + (size_t)ga * DIMS + col);
                ss = fmaf(v.x, v.x, ss);
                ss = fmaf(v.y, v.y, ss);
                ss = fmaf(v.z, v.z, ss);
                ss = fmaf(v.w, v.w, ss);

                const __nv_bfloat16 hx = __float2bfloat16_rn(v.x);
                const __nv_bfloat16 hy = __float2bfloat16_rn(v.y);
                const __nv_bfloat16 hz = __float2bfloat16_rn(v.z);
                const __nv_bfloat16 hw = __float2bfloat16_rn(v.w);

                __nv_bfloat162 p01, p23;
                p01.x = hx; p01.y = hy; p23.x = hz; p23.y = hw;
                *reinterpret_cast<__nv_bfloat162*>(&sA[a * A_STRIDE + col])     = p01;
                *reinterpret_cast<__nv_bfloat162*>(&sA[a * A_STRIDE + col + 2]) = p23;

                float4 e;
                e.x = 2.f * v.x - __bfloat162float(hx);
                e.y = 2.f * v.y - __bfloat162float(hy);
                e.z = 2.f * v.z - __bfloat162float(hz);
                e.w = 2.f * v.w - __bfloat162float(hw);
                *reinterpret_cast<float4*>(&sE[a * E_STRIDE + col]) = e;
            }
            ss += __shfl_xor_sync(0xffffffffu, ss, 1);
            ss += __shfl_xor_sync(0xffffffffu, ss, 2);
            if (part == 0) sInv[a] = (ss > 0.f) ? 1.f / ss : 0.f;
        }
        __syncthreads();

        // ---- mma mainloop: acc = A * (Qhi + Qlo) ----
        float acc[2][4][4];
        #pragma unroll
        for (int mt = 0; mt < 2; mt++)
            #pragma unroll
            for (int nt = 0; nt < 4; nt++)
                #pragma unroll
                for (int c = 0; c < 4; c++) acc[mt][nt][c] = 0.f;

        #pragma unroll
        for (int u = 0; u < 8; u++) {
            uint32_t afrag[2][4];
            #pragma unroll
            for (int mt = 0; mt < 2; mt++) {
                const __nv_bfloat16* ar =
                    sA + (mrow0 + mt * 16 + g) * A_STRIDE + (u * 16 + tg * 2);
                afrag[mt][0] = *reinterpret_cast<const uint32_t*>(ar);
                afrag[mt][1] = *reinterpret_cast<const uint32_t*>(ar + 8 * A_STRIDE);
                afrag[mt][2] = *reinterpret_cast<const uint32_t*>(ar + 8);
                afrag[mt][3] = *reinterpret_cast<const uint32_t*>(ar + 8 * A_STRIDE + 8);
            }
            #pragma unroll
            for (int nt = 0; nt < 4; nt++) {
                const int t = ng * 4 + nt;
                const int bidx = ((u * 16 + t) * 32 + lid) * 2;
                const uint2 bh = *reinterpret_cast<const uint2*>(sBhi + bidx);
                const uint2 bl = *reinterpret_cast<const uint2*>(sBlo + bidx);
                #pragma unroll
                for (int mt = 0; mt < 2; mt++) {
                    mma_bf16(acc[mt][nt], afrag[mt], bh.x, bh.y);
                    mma_bf16(acc[mt][nt], afrag[mt], bl.x, bl.y);
                }
            }
        }

        // ---- epilogue: partial = dot(E_row, Y_row) over this warp's 32 cols
        #pragma unroll
        for (int mt = 0; mt < 2; mt++) {
            const int r0 = mrow0 + mt * 16 + g;
            const int r1 = r0 + 8;
            float p0 = 0.f, p1 = 0.f;
            #pragma unroll
            for (int nt = 0; nt < 4; nt++) {
                const int c = ng * 32 + nt * 8 + tg * 2;
                const float2 e0 = *reinterpret_cast<const float2*>(&sE[r0 * E_STRIDE + c]);
                const float2 e1 = *reinterpret_cast<const float2*>(&sE[r1 * E_STRIDE + c]);
                p0 = fmaf(e0.x, acc[mt][nt][0], p0);
                p0 = fmaf(e0.y, acc[mt][nt][1], p0);
                p1 = fmaf(e1.x, acc[mt][nt][2], p1);
                p1 = fmaf(e1.y, acc[mt][nt][3], p1);
            }
            p0 += __shfl_xor_sync(0xffffffffu, p0, 1);
            p0 += __shfl_xor_sync(0xffffffffu, p0, 2);
            p1 += __shfl_xor_sync(0xffffffffu, p1, 1);
            p1 += __shfl_xor_sync(0xffffffffu, p1, 2);
            if (tg == 0) {
                sPart[r0 * 4 + ng] = p0;
                sPart[r1 * 4 + ng] = p1;
            }
        }
        __syncthreads();

        if (tid < TILE_M) {
            const float* pr = sPart + tid * 4;
            const float v = ((pr[0] + pr[1]) + pr[2]) + pr[3];
            const int ga = base + tid;
            if (ga < N) g_atomval[ga] = v * sInv[tid];
        }
    }
}

// ---------------------------------------------------------------------------
// Kernel C: segment sum using precomputed boundaries. One warp / structure.
// ---------------------------------------------------------------------------
__global__ void seg_sum(float* __restrict__ out, int S)
{
    const int s = blockIdx.x * (blockDim.x >> 5) + (threadIdx.x >> 5);
    if (s >= S) return;
    const int lane = threadIdx.x & 31;

    const int lo = g_start[s];
    const int hi = g_start[s + 1];

    float sum = 0.f;
    for (int i = lo + lane; i < hi; i += 32)
        sum += g_atomval[i];
    #pragma unroll
    for (int off = 16; off; off >>= 1)
        sum += __shfl_xor_sync(0xffffffffu, sum, off);
    if (lane == 0) out[s] = sum;
}

// ---------------------------------------------------------------------------
// Launch.
// ---------------------------------------------------------------------------
extern "C" void kernel_launch(void* const* d_in, const int* in_sizes, int n_in,
                              void* d_out, int out_size)
{
    const float* ps   = (const float*)d_in[0];
    const float* sp   = (const float*)d_in[1];
    const float* w    = (const float*)d_in[2];
    const int*   aseg = (const int*)d_in[3];
    const int*   sseg = (const int*)d_in[4];

    const int N = in_sizes[3];
    const int M = in_sizes[4];
    const int S = out_size;          // P == 1
    float* out = (float*)d_out;

    mark_starts<<<(N + 255) / 256, 256>>>(aseg, N, S);

    compute_Q_partial<<<QP_BLOCKS, 256>>>(sp, w, sseg, M);
    reduce_Q<<<DIMS * DIMS / 256, 256>>>();

    cudaFuncSetAttribute(atom_quadform_mma,
                         cudaFuncAttributeMaxDynamicSharedMemorySize, SMEM_TOTAL_B);
    const int numTiles = (N + TILE_M - 1) / TILE_M;
    const int grid = numTiles < 148 ? numTiles : 148;
    atom_quadform_mma<<<grid, THREADS_B, SMEM_TOTAL_B>>>(ps, N, numTiles);

    seg_sum<<<(S + 7) / 8, 256>>>(out, S);
}

// round 13
// speedup vs baseline: 2.3665x; 1.0279x over previous
#include <cuda_runtime.h>
#include <cuda_bf16.h>
#include <cstdint>
#include <cstddef>

// ---------------------------------------------------------------------------
// FullGapModel, specialized: D = 128, P = 1, zeta = 2.
// out[s] = sum_{atoms a in s} ps_a^T Q ps_a / ||ps_a||^2,
//   Q = sum_m w[seg_sup[m]] * sp_m sp_m^T  (128x128, symmetric).
// Main kernel: bf16 mma.sync (m16n8k16) GEMM Y = H * Q with Q split into
// bf16 hi+lo (both accumulated into the same f32 C), A-side error
// compensation (val = dot(2*ps - h, Y) / ||ps||^2), and register-level
// software pipelining of the next tile's global loads across the MMA phase.
// ---------------------------------------------------------------------------

#define DIMS 128
constexpr int TILE_M     = 128;     // atoms per CTA tile
constexpr int THREADS_B  = 512;     // 16 warps: 4 (m) x 4 (n)
constexpr int MAX_ATOMS  = 131072;  // >= N = 100000
constexpr int QP_BLOCKS  = 80;
constexpr int MAX_STRUCT = 8192;    // >= S = 2000

__device__ float    g_Qpart[QP_BLOCKS][DIMS * DIMS];
__device__ uint32_t g_Bhi_pack[8192];   // bf16x2 fragment-packed Q hi
__device__ uint32_t g_Blo_pack[8192];   // bf16x2 fragment-packed Q lo
__device__ float    g_atomval[MAX_ATOMS];
__device__ int      g_start[MAX_STRUCT + 1];

// ---------------------------------------------------------------------------
// Kernel A1: partial Q over M-chunks. Thread owns 8x8 register tile of Q.
// ---------------------------------------------------------------------------
__global__ __launch_bounds__(256) void compute_Q_partial(
    const float* __restrict__ sp,
    const float* __restrict__ weights,
    const int*   __restrict__ supseg,
    int M)
{
    __shared__ float srow[8][DIMS];
    __shared__ float sw[8];

    const int chunk = (M + QP_BLOCKS - 1) / QP_BLOCKS;
    const int m_lo = blockIdx.x * chunk;
    const int m_hi = min(M, m_lo + chunk);

    const int i0 = (threadIdx.x >> 4) * 8;
    const int j0 = (threadIdx.x & 15) * 8;

    float acc[8][8];
    #pragma unroll
    for (int a = 0; a < 8; a++)
        #pragma unroll
        for (int b = 0; b < 8; b++) acc[a][b] = 0.f;

    for (int m0 = m_lo; m0 < m_hi; m0 += 8) {
        const int rows = min(8, m_hi - m0);
        __syncthreads();
        for (int idx = threadIdx.x; idx < rows * DIMS; idx += 256)
            srow[idx >> 7][idx & 127] = sp[(size_t)m0 * DIMS + idx];
        if (threadIdx.x < rows)
            sw[threadIdx.x] = weights[supseg[m0 + threadIdx.x]];
        __syncthreads();

        #pragma unroll 8
        for (int u = 0; u < rows; u++) {
            float si[8], sj[8];
            *reinterpret_cast<float4*>(&si[0]) = *reinterpret_cast<float4*>(&srow[u][i0]);
            *reinterpret_cast<float4*>(&si[4]) = *reinterpret_cast<float4*>(&srow[u][i0 + 4]);
            *reinterpret_cast<float4*>(&sj[0]) = *reinterpret_cast<float4*>(&srow[u][j0]);
            *reinterpret_cast<float4*>(&sj[4]) = *reinterpret_cast<float4*>(&srow[u][j0 + 4]);
            const float wu = sw[u];
            #pragma unroll
            for (int a = 0; a < 8; a++) {
                const float siw = wu * si[a];
                #pragma unroll
                for (int b = 0; b < 8; b++)
                    acc[a][b] = fmaf(siw, sj[b], acc[a][b]);
            }
        }
    }

    float* dst = g_Qpart[blockIdx.x];
    #pragma unroll
    for (int a = 0; a < 8; a++)
        #pragma unroll
        for (int b = 0; b < 8; b += 4)
            *reinterpret_cast<float4*>(&dst[(i0 + a) * DIMS + j0 + b]) =
                *reinterpret_cast<float4*>(&acc[a][b]);
}

// ---------------------------------------------------------------------------
// Kernel A2: reduce partials; emit bf16 hi/lo Q in mma fragment-packed order.
// For element (n, k): B-frag of tile (t = n/8, u = k/16) at lane
// l = (n%8)*4 + ((k%8)>>1), reg r = (k%16)/8, halfword = k&1.
// ---------------------------------------------------------------------------
__global__ void reduce_Q()
{
    const int idx = blockIdx.x * blockDim.x + threadIdx.x;   // 0..16383
    const int n = idx >> 7, k = idx & 127;
    float s = 0.f;
    #pragma unroll 8
    for (int p = 0; p < QP_BLOCKS; p++)
        s += g_Qpart[p][idx];

    const __nv_bfloat16 hi = __float2bfloat16_rn(s);
    const __nv_bfloat16 lo = __float2bfloat16_rn(s - __bfloat162float(hi));

    const int u = k >> 4, t = n >> 3;
    const int g = n & 7, kk = k & 15;
    const int r = kk >> 3, tg = (kk & 7) >> 1, half = kk & 1;
    const int u32idx = ((u * 16 + t) * 32 + (g * 4 + tg)) * 2 + r;

    reinterpret_cast<__nv_bfloat16*>(g_Bhi_pack)[u32idx * 2 + half] = hi;
    reinterpret_cast<__nv_bfloat16*>(g_Blo_pack)[u32idx * 2 + half] = lo;
}

// ---------------------------------------------------------------------------
// Kernel D: structure boundaries from the sorted atom_segments array.
// ---------------------------------------------------------------------------
__global__ void mark_starts(const int* __restrict__ aseg, int N, int S)
{
    const int i = blockIdx.x * blockDim.x + threadIdx.x;
    if (i >= N) return;
    const int cur = aseg[i];
    const int prev = (i == 0) ? -1 : aseg[i - 1];
    for (int s = prev + 1; s <= cur; s++) g_start[s] = i;
    if (i == N - 1)
        for (int s = cur + 1; s <= S; s++) g_start[s] = N;
}

// ---------------------------------------------------------------------------
// Kernel B: HMMA quadratic form with register-prefetch pipelining.
// smem: A (bf16, 128 x stride136), E = 2*ps - h (f32, 128 x stride132),
//       Bhi/Blo packed (32KB each, tile-invariant), spart[128][4], inv[128].
// ---------------------------------------------------------------------------
constexpr int A_STRIDE  = 136;                         // bf16 units
constexpr int E_STRIDE  = 132;                         // f32 units
constexpr int OFF_A     = 0;                           // 128*136*2 = 34816
constexpr int OFF_E     = 34816;                       // 128*132*4 = 67584
constexpr int OFF_BHI   = OFF_E + 67584;               // 102400, 32768 B
constexpr int OFF_BLO   = OFF_BHI + 32768;             // 135168, 32768 B
constexpr int OFF_SPART = OFF_BLO + 32768;             // 167936, 2048 B
constexpr int OFF_INV   = OFF_SPART + 2048;            // 169984, 512 B
constexpr int SMEM_TOTAL_B = OFF_INV + 512;            // 170496 B

__device__ __forceinline__ void mma_bf16(float* d, const uint32_t* a,
                                         uint32_t b0, uint32_t b1) {
    asm volatile(
        "mma.sync.aligned.m16n8k16.row.col.f32.bf16.bf16.f32 "
        "{%0,%1,%2,%3}, {%4,%5,%6,%7}, {%8,%9}, {%0,%1,%2,%3};"
        : "+f"(d[0]), "+f"(d[1]), "+f"(d[2]), "+f"(d[3])
        : "r"(a[0]), "r"(a[1]), "r"(a[2]), "r"(a[3]), "r"(b0), "r"(b1));
}

__global__ __launch_bounds__(THREADS_B) void atom_quadform_mma(
    const float* __restrict__ ps, int N, int numTiles)
{
    extern __shared__ char smem[];
    __nv_bfloat16* sA = reinterpret_cast<__nv_bfloat16*>(smem + OFF_A);
    float* sE    = reinterpret_cast<float*>(smem + OFF_E);
    float* sPart = reinterpret_cast<float*>(smem + OFF_SPART);
    float* sInv  = reinterpret_cast<float*>(smem + OFF_INV);
    const uint32_t* sBhi = reinterpret_cast<const uint32_t*>(smem + OFF_BHI);
    const uint32_t* sBlo = reinterpret_cast<const uint32_t*>(smem + OFF_BLO);

    const int tid = threadIdx.x;
    const int wid = tid >> 5;
    const int lid = tid & 31;
    const int g  = lid >> 2;
    const int tg = lid & 3;
    const int mrow0 = (wid & 3) * 32;
    const int ng    = wid >> 2;          // n column group (32 cols)

    const int arow  = tid >> 2;          // loader row 0..127
    const int apart = tid & 3;           // loader col chunk of 32

    // Stage packed B (tile-invariant) into smem once.
    {
        const uint4* srcH = reinterpret_cast<const uint4*>(g_Bhi_pack);
        const uint4* srcL = reinterpret_cast<const uint4*>(g_Blo_pack);
        uint4* dstH = reinterpret_cast<uint4*>(smem + OFF_BHI);
        uint4* dstL = reinterpret_cast<uint4*>(smem + OFF_BLO);
        for (int i = tid; i < 2048; i += THREADS_B) {
            dstH[i] = srcH[i];
            dstL[i] = srcL[i];
        }
    }

    const int stride = gridDim.x;

    // Prefetch first tile into registers.
    float4 v[8];
    {
        const int ga = blockIdx.x * TILE_M + arow;
        #pragma unroll
        for (int q = 0; q < 8; q++) {
            const int col = apart * 32 + q * 4;
            v[q] = (ga < N)
                 ? *reinterpret_cast<const float4*>(ps + (size_t)ga * DIMS + col)
                 : make_float4(0.f, 0.f, 0.f, 0.f);
        }
    }
    __syncthreads();   // B staged

    for (int tile = blockIdx.x; tile < numTiles; tile += stride) {
        const int base = tile * TILE_M;

        // ---- store phase: regs -> bf16 A + f32 E(=2ps-h) + inv ----
        {
            float ss = 0.f;
            #pragma unroll
            for (int q = 0; q < 8; q++) {
                const int col = apart * 32 + q * 4;
                const float4 pv = v[q];
                ss = fmaf(pv.x, pv.x, ss);
                ss = fmaf(pv.y, pv.y, ss);
                ss = fmaf(pv.z, pv.z, ss);
                ss = fmaf(pv.w, pv.w, ss);

                const __nv_bfloat16 hx = __float2bfloat16_rn(pv.x);
                const __nv_bfloat16 hy = __float2bfloat16_rn(pv.y);
                const __nv_bfloat16 hz = __float2bfloat16_rn(pv.z);
                const __nv_bfloat16 hw = __float2bfloat16_rn(pv.w);

                __nv_bfloat162 p01, p23;
                p01.x = hx; p01.y = hy; p23.x = hz; p23.y = hw;
                *reinterpret_cast<__nv_bfloat162*>(&sA[arow * A_STRIDE + col])     = p01;
                *reinterpret_cast<__nv_bfloat162*>(&sA[arow * A_STRIDE + col + 2]) = p23;

                float4 e;
                e.x = 2.f * pv.x - __bfloat162float(hx);
                e.y = 2.f * pv.y - __bfloat162float(hy);
                e.z = 2.f * pv.z - __bfloat162float(hz);
                e.w = 2.f * pv.w - __bfloat162float(hw);
                *reinterpret_cast<float4*>(&sE[arow * E_STRIDE + col]) = e;
            }
            ss += __shfl_xor_sync(0xffffffffu, ss, 1);
            ss += __shfl_xor_sync(0xffffffffu, ss, 2);
            if (apart == 0) sInv[arow] = (ss > 0.f) ? 1.f / ss : 0.f;
        }

        // ---- prefetch next tile (overlaps the MMA + epilogue below) ----
        {
            const int ntile = tile + stride;
            if (ntile < numTiles) {
                const int ga = ntile * TILE_M + arow;
                #pragma unroll
                for (int q = 0; q < 8; q++) {
                    const int col = apart * 32 + q * 4;
                    v[q] = (ga < N)
                         ? *reinterpret_cast<const float4*>(ps + (size_t)ga * DIMS + col)
                         : make_float4(0.f, 0.f, 0.f, 0.f);
                }
            }
        }
        __syncthreads();   // A/E/inv visible

        // ---- mma mainloop: acc = A * (Qhi + Qlo) ----
        float acc[2][4][4];
        #pragma unroll
        for (int mt = 0; mt < 2; mt++)
            #pragma unroll
            for (int nt = 0; nt < 4; nt++)
                #pragma unroll
                for (int c = 0; c < 4; c++) acc[mt][nt][c] = 0.f;

        #pragma unroll
        for (int u = 0; u < 8; u++) {
            uint32_t afrag[2][4];
            #pragma unroll
            for (int mt = 0; mt < 2; mt++) {
                const __nv_bfloat16* ar =
                    sA + (mrow0 + mt * 16 + g) * A_STRIDE + (u * 16 + tg * 2);
                afrag[mt][0] = *reinterpret_cast<const uint32_t*>(ar);
                afrag[mt][1] = *reinterpret_cast<const uint32_t*>(ar + 8 * A_STRIDE);
                afrag[mt][2] = *reinterpret_cast<const uint32_t*>(ar + 8);
                afrag[mt][3] = *reinterpret_cast<const uint32_t*>(ar + 8 * A_STRIDE + 8);
            }
            #pragma unroll
            for (int nt = 0; nt < 4; nt++) {
                const int t = ng * 4 + nt;
                const int bidx = ((u * 16 + t) * 32 + lid) * 2;
                const uint2 bh = *reinterpret_cast<const uint2*>(sBhi + bidx);
                const uint2 bl = *reinterpret_cast<const uint2*>(sBlo + bidx);
                #pragma unroll
                for (int mt = 0; mt < 2; mt++) {
                    mma_bf16(acc[mt][nt], afrag[mt], bh.x, bh.y);
                    mma_bf16(acc[mt][nt], afrag[mt], bl.x, bl.y);
                }
            }
        }

        // ---- epilogue: partial = dot(E_row, Y_row) over this warp's 32 cols
        #pragma unroll
        for (int mt = 0; mt < 2; mt++) {
            const int r0 = mrow0 + mt * 16 + g;
            const int r1 = r0 + 8;
            float p0 = 0.f, p1 = 0.f;
            #pragma unroll
            for (int nt = 0; nt < 4; nt++) {
                const int c = ng * 32 + nt * 8 + tg * 2;
                const float2 e0 = *reinterpret_cast<const float2*>(&sE[r0 * E_STRIDE + c]);
                const float2 e1 = *reinterpret_cast<const float2*>(&sE[r1 * E_STRIDE + c]);
                p0 = fmaf(e0.x, acc[mt][nt][0], p0);
                p0 = fmaf(e0.y, acc[mt][nt][1], p0);
                p1 = fmaf(e1.x, acc[mt][nt][2], p1);
                p1 = fmaf(e1.y, acc[mt][nt][3], p1);
            }
            p0 += __shfl_xor_sync(0xffffffffu, p0, 1);
            p0 += __shfl_xor_sync(0xffffffffu, p0, 2);
            p1 += __shfl_xor_sync(0xffffffffu, p1, 1);
            p1 += __shfl_xor_sync(0xffffffffu, p1, 2);
            if (tg == 0) {
                sPart[r0 * 4 + ng] = p0;
                sPart[r1 * 4 + ng] = p1;
            }
        }
        __syncthreads();   // sPart visible

        if (tid < TILE_M) {
            const float* pr = sPart + tid * 4;
            const float vv = ((pr[0] + pr[1]) + pr[2]) + pr[3];
            const int ga = base + tid;
            if (ga < N) g_atomval[ga] = vv * sInv[tid];
        }
        __syncthreads();   // all reads of A/E/sPart/sInv done before next store
    }
}

// ---------------------------------------------------------------------------
// Kernel C: segment sum using precomputed boundaries. One warp / structure.
// ---------------------------------------------------------------------------
__global__ void seg_sum(float* __restrict__ out, int S)
{
    const int s = blockIdx.x * (blockDim.x >> 5) + (threadIdx.x >> 5);
    if (s >= S) return;
    const int lane = threadIdx.x & 31;

    const int lo = g_start[s];
    const int hi = g_start[s + 1];

    float sum = 0.f;
    for (int i = lo + lane; i < hi; i += 32)
        sum += g_atomval[i];
    #pragma unroll
    for (int off = 16; off; off >>= 1)
        sum += __shfl_xor_sync(0xffffffffu, sum, off);
    if (lane == 0) out[s] = sum;
}

// ---------------------------------------------------------------------------
// Launch.
// ---------------------------------------------------------------------------
extern "C" void kernel_launch(void* const* d_in, const int* in_sizes, int n_in,
                              void* d_out, int out_size)
{
    const float* ps   = (const float*)d_in[0];
    const float* sp   = (const float*)d_in[1];
    const float* w    = (const float*)d_in[2];
    const int*   aseg = (const int*)d_in[3];
    const int*   sseg = (const int*)d_in[4];

    const int N = in_sizes[3];
    const int M = in_sizes[4];
    const int S = out_size;          // P == 1
    float* out = (float*)d_out;

    mark_starts<<<(N + 255) / 256, 256>>>(aseg, N, S);

    compute_Q_partial<<<QP_BLOCKS, 256>>>(sp, w, sseg, M);
    reduce_Q<<<DIMS * DIMS / 256, 256>>>();

    cudaFuncSetAttribute(atom_quadform_mma,
                         cudaFuncAttributeMaxDynamicSharedMemorySize, SMEM_TOTAL_B);
    const int numTiles = (N + TILE_M - 1) / TILE_M;
    const int grid = numTiles < 148 ? numTiles : 148;
    atom_quadform_mma<<<grid, THREADS_B, SMEM_TOTAL_B>>>(ps, N, numTiles);

    seg_sum<<<(S + 7) / 8, 256>>>(out, S);
}